// round 9
// baseline (speedup 1.0000x reference)
#include <cuda_runtime.h>
#include <cuda_bf16.h>
#include <cstdint>

// NeRF raw2outputs. R9: persistent CTAs + double-buffered cp.async.bulk
// pipeline. 456 blocks (~3/SM), each grid-strides over 8-ray tiles; stage s^1
// is being TMA-filled while all 8 warps compute stage s. Per-stage full/empty
// mbarriers only -- no __syncthreads in the steady-state loop.
//
// Output layout (tuple flattened in order), N = num rays:
//   [0 , 3N)     rgb_map   [N,3]
//   [3N, 4N)     disp_map  [N,1]
//   [4N, 5N)     acc_map   [N,1]
//   [5N, 197N)   weights   [N,192]
//   [197N, 198N) depth_map [N,1]

#define FULL 0xffffffffu
#define NSAMP 192
#define NCHUNK 6
#define RAYS_PER_TILE 8
#define INF_DIST 1e10f
#define NBLOCKS 456

// dynamic smem layout (bytes):
//   raw stage0 @ 0        : 8*192*16 = 24576
//   raw stage1 @ 24576    : 24576
//   z   stage0 @ 49152    : 8*192*4  = 6144
//   z   stage1 @ 55296    : 6144
//   mbarriers  @ 61440    : full0, full1, empty0, empty1 (4 * 8B)
#define SMEM_RAW_OFF   0
#define SMEM_Z_OFF     49152
#define SMEM_MBAR_OFF  61440
#define SMEM_BYTES     61504

__device__ __forceinline__ uint32_t smem_u32(const void* p) {
    uint32_t a;
    asm("{ .reg .u64 t; cvta.to.shared.u64 t, %1; cvt.u32.u64 %0, t; }"
        : "=r"(a) : "l"(p));
    return a;
}

__device__ __forceinline__ float fast_sigmoid(float x) {
    float t;
    asm("tanh.approx.f32 %0, %1;" : "=f"(t) : "f"(0.5f * x));
    return fmaf(0.5f, t, 0.5f);
}

__device__ __forceinline__ void mbar_wait(uint32_t mbar, uint32_t par) {
    asm volatile(
        "{\n .reg .pred P1;\n"
        "W%=:\n"
        " mbarrier.try_wait.parity.acquire.cta.shared::cta.b64 P1, [%0], %1, 0x989680;\n"
        " @P1 bra.uni D%=;\n"
        " bra.uni W%=;\n"
        "D%=:\n}"
        :: "r"(mbar), "r"(par) : "memory");
}

__device__ __forceinline__ void issue_tile(uint32_t raw_dst, uint32_t z_dst,
                                           uint32_t fullbar,
                                           const float4* gsrc_raw,
                                           const float*  gsrc_z,
                                           int nrays)
{
    const uint32_t rawb = (uint32_t)nrays * NSAMP * 16u;
    const uint32_t zb   = (uint32_t)nrays * NSAMP * 4u;
    asm volatile("mbarrier.arrive.expect_tx.shared.b64 _, [%0], %1;"
                 :: "r"(fullbar), "r"(rawb + zb) : "memory");
    asm volatile("cp.async.bulk.shared::cta.global.mbarrier::complete_tx::bytes"
                 " [%0], [%1], %2, [%3];"
                 :: "r"(raw_dst), "l"(gsrc_raw), "r"(rawb), "r"(fullbar) : "memory");
    asm volatile("cp.async.bulk.shared::cta.global.mbarrier::complete_tx::bytes"
                 " [%0], [%1], %2, [%3];"
                 :: "r"(z_dst), "l"(gsrc_z), "r"(zb), "r"(fullbar) : "memory");
}

__global__ __launch_bounds__(256)
void nerf_render_kernel(const float4* __restrict__ raw4,
                        const float*  __restrict__ z_vals,
                        const float*  __restrict__ rays_d,
                        float* __restrict__ out,
                        int N)
{
    extern __shared__ char smem[];
    float4* s_raw = (float4*)(smem + SMEM_RAW_OFF);   // stage s at +s*1536 elems
    float*  s_z   = (float*)(smem + SMEM_Z_OFF);      // stage s at +s*1536 elems
    const uint32_t mb = smem_u32(smem + SMEM_MBAR_OFF);
    // full[s] = mb + 8*s ; empty[s] = mb + 16 + 8*s

    const int warp = threadIdx.x >> 5;
    const int lane = threadIdx.x & 31;
    const int G = gridDim.x;
    const long T = (N + RAYS_PER_TILE - 1) / RAYS_PER_TILE;

    if (threadIdx.x == 0) {
        asm volatile("mbarrier.init.shared.b64 [%0], 1;" :: "r"(mb +  0) : "memory");
        asm volatile("mbarrier.init.shared.b64 [%0], 1;" :: "r"(mb +  8) : "memory");
        asm volatile("mbarrier.init.shared.b64 [%0], 8;" :: "r"(mb + 16) : "memory");
        asm volatile("mbarrier.init.shared.b64 [%0], 8;" :: "r"(mb + 24) : "memory");
        asm volatile("fence.proxy.async.shared::cta;" ::: "memory");
    }
    __syncthreads();

    // prologue: fill both stages
    if (threadIdx.x == 0) {
#pragma unroll
        for (int k = 0; k < 2; ++k) {
            const long t = (long)blockIdx.x + (long)k * G;
            if (t < T) {
                const int nrays = min(RAYS_PER_TILE, N - (int)(t * RAYS_PER_TILE));
                issue_tile(smem_u32(s_raw + k * 1536), smem_u32(s_z + k * 1536),
                           mb + 8 * k,
                           raw4 + t * (RAYS_PER_TILE * NSAMP / 1),
                           z_vals + t * (RAYS_PER_TILE * NSAMP),
                           nrays);
            }
        }
    }

    float* __restrict__ wout = out + (long)5 * N;

    int j = 0;
    for (long t = blockIdx.x; t < T; t += G, ++j) {
        const int s = j & 1;
        const uint32_t par = (uint32_t)((j >> 1) & 1);
        mbar_wait(mb + 8 * s, par);                       // full, acquire

        const int ray = (int)(t * RAYS_PER_TILE) + warp;
        if (ray < N) {
            const float4* __restrict__ rb = s_raw + s * 1536 + warp * NSAMP;
            const float*  __restrict__ zb = s_z   + s * 1536 + warp * NSAMP;
            const long base = (long)ray * NSAMP;

            const float dx = rays_d[3 * ray + 0];
            const float dy = rays_d[3 * ray + 1];
            const float dz = rays_d[3 * ray + 2];
            const float nrm = sqrtf(dx * dx + dy * dy + dz * dz);

            float alpha[NCHUNK], p[NCHUNK];
#pragma unroll
            for (int c = 0; c < NCHUNK; ++c) {
                const int i = c * 32 + lane;
                const float z  = zb[i];
                const float zn = (i == NSAMP - 1) ? INF_DIST : zb[i + 1];
                const float dist = (zn - z) * nrm;
                const float sigma = fmaxf(rb[i].w, 0.f);
                alpha[c] = 1.f - __expf(-sigma * dist);
                p[c] = 1.f - alpha[c] + 1e-10f;
            }

#pragma unroll
            for (int off = 1; off < 32; off <<= 1) {
#pragma unroll
                for (int c = 0; c < NCHUNK; ++c) {
                    const float u = __shfl_up_sync(FULL, p[c], off);
                    if (lane >= off) p[c] *= u;
                }
            }

            float exc[NCHUNK], tot[NCHUNK];
#pragma unroll
            for (int c = 0; c < NCHUNK; ++c) {
                exc[c] = __shfl_up_sync(FULL, p[c], 1);
                if (lane == 0) exc[c] = 1.f;
                tot[c] = __shfl_sync(FULL, p[c], 31);
            }

            float carry[NCHUNK];
            carry[0] = 1.f;
#pragma unroll
            for (int c = 1; c < NCHUNK; ++c)
                carry[c] = carry[c - 1] * tot[c - 1];

            float r_sum = 0.f, g_sum = 0.f, b_sum = 0.f, d_sum = 0.f, a_sum = 0.f;
#pragma unroll
            for (int c = 0; c < NCHUNK; ++c) {
                const int i = c * 32 + lane;
                const float w = alpha[c] * carry[c] * exc[c];
                const float4 rv = rb[i];

                r_sum += w * fast_sigmoid(rv.x);
                g_sum += w * fast_sigmoid(rv.y);
                b_sum += w * fast_sigmoid(rv.z);
                d_sum += w * zb[i];
                a_sum += w;

                __stcs(&wout[base + i], w);
            }

#pragma unroll
            for (int off = 16; off; off >>= 1) {
                r_sum += __shfl_down_sync(FULL, r_sum, off);
                g_sum += __shfl_down_sync(FULL, g_sum, off);
                b_sum += __shfl_down_sync(FULL, b_sum, off);
                d_sum += __shfl_down_sync(FULL, d_sum, off);
                a_sum += __shfl_down_sync(FULL, a_sum, off);
            }

            if (lane == 0) {
                out[3 * ray + 0] = r_sum;
                out[3 * ray + 1] = g_sum;
                out[3 * ray + 2] = b_sum;

                const float acc = a_sum;
                float depth = d_sum;
                if (acc <= 1e-10f) depth = INF_DIST;
                const float ratio = __fdividef(depth, acc);
                const float disp  = __fdividef(1.f, fmaxf(1e-10f, ratio));

                out[(long)3 * N + ray]   = disp;
                out[(long)4 * N + ray]   = acc;
                out[(long)197 * N + ray] = depth;
            }
        }

        __syncwarp();
        if (lane == 0)
            asm volatile("mbarrier.arrive.shared.b64 _, [%0];"
                         :: "r"(mb + 16 + 8 * s) : "memory");

        // producer: refill this stage for tile t + 2G
        if (threadIdx.x == 0) {
            const long tn = t + 2L * G;
            if (tn < T) {
                mbar_wait(mb + 16 + 8 * s, par);          // empty
                const int nrays = min(RAYS_PER_TILE, N - (int)(tn * RAYS_PER_TILE));
                issue_tile(smem_u32(s_raw + s * 1536), smem_u32(s_z + s * 1536),
                           mb + 8 * s,
                           raw4 + tn * (RAYS_PER_TILE * NSAMP),
                           z_vals + tn * (RAYS_PER_TILE * NSAMP),
                           nrays);
            }
        }
    }
}

extern "C" void kernel_launch(void* const* d_in, const int* in_sizes, int n_in,
                              void* d_out, int out_size)
{
    const float4* raw4   = (const float4*)d_in[0];
    const float*  z_vals = (const float*)d_in[1];
    const float*  rays_d = (const float*)d_in[2];
    float* out = (float*)d_out;

    const int N = in_sizes[2] / 3;          // num rays from rays_d

    static int attr_done = 0;
    if (!attr_done) {
        cudaFuncSetAttribute(nerf_render_kernel,
                             cudaFuncAttributeMaxDynamicSharedMemorySize,
                             SMEM_BYTES);
        attr_done = 1;
    }
    nerf_render_kernel<<<NBLOCKS, 256, SMEM_BYTES>>>(raw4, z_vals, rays_d, out, N);
}

// round 10
// speedup vs baseline: 1.7652x; 1.7652x over previous
#include <cuda_runtime.h>
#include <cuda_bf16.h>

// NeRF raw2outputs — FINAL (R7 structure, converged at ~47.6us).
// One warp per ray, 6 chunks of 32 samples; all 12 global loads front-batched
// (per-warp MLP is the binding resource: regs 48 / occ 52% / DRAM 79-80%).
// Streaming cache hints on read-once/write-once streams; single-MUFU
// tanh.approx sigmoid; 6 interleaved warp product-scans with a cross-chunk
// carry prefix instead of a serial chain.
//
// Session evidence: occupancy-raising variants (2 warps/ray, launch_bounds
// caps, smem staging, persistent TMA pipeline) all reduced DRAM throughput;
// in-flight-bytes analysis shows latency hiding is 10x over-provisioned, so
// ~6.3 TB/s is the achievable mixed-stream DRAM roof for this 5:1 R:W mix.
//
// Output layout (tuple flattened in order), N = num rays:
//   [0 , 3N)     rgb_map   [N,3]
//   [3N, 4N)     disp_map  [N,1]
//   [4N, 5N)     acc_map   [N,1]
//   [5N, 197N)   weights   [N,192]
//   [197N, 198N) depth_map [N,1]

#define FULL 0xffffffffu
#define NSAMP 192
#define NCHUNK 6
#define INF_DIST 1e10f

__device__ __forceinline__ float fast_sigmoid(float x) {
    float t;
    asm("tanh.approx.f32 %0, %1;" : "=f"(t) : "f"(0.5f * x));
    return fmaf(0.5f, t, 0.5f);
}

__global__ __launch_bounds__(256)
void nerf_render_kernel(const float4* __restrict__ raw4,
                        const float*  __restrict__ z_vals,
                        const float*  __restrict__ rays_d,
                        float* __restrict__ out,
                        int N)
{
    const int warp_in_blk = threadIdx.x >> 5;
    const int lane        = threadIdx.x & 31;
    const int ray = blockIdx.x * (blockDim.x >> 5) + warp_in_blk;
    if (ray >= N) return;

    const long base = (long)ray * NSAMP;

    // ---- front-batch ALL global loads (12 independent LDGs in flight) ----
    float4 rv[NCHUNK];
    float  zv[NCHUNK];
#pragma unroll
    for (int c = 0; c < NCHUNK; ++c)
        rv[c] = __ldcs(&raw4[base + c * 32 + lane]);     // read-once stream
#pragma unroll
    for (int c = 0; c < NCHUNK; ++c)
        zv[c] = __ldcs(&z_vals[base + c * 32 + lane]);   // read-once stream

    const float dx = rays_d[3 * ray + 0];
    const float dy = rays_d[3 * ray + 1];
    const float dz = rays_d[3 * ray + 2];
    const float nrm = sqrtf(dx * dx + dy * dy + dz * dz);

    // ---- per-sample alpha and t = 1-alpha+eps (independent across chunks) ----
    float alpha[NCHUNK], p[NCHUNK];
#pragma unroll
    for (int c = 0; c < NCHUNK; ++c) {
        const float z  = zv[c];
        const float zn = __shfl_down_sync(FULL, z, 1);
        float dist;
        if (c < NCHUNK - 1) {
            const float zfn = __shfl_sync(FULL, zv[c + 1], 0);
            dist = (lane == 31) ? (zfn - z) : (zn - z);
        } else {
            dist = (lane == 31) ? INF_DIST : (zn - z);
        }
        dist *= nrm;
        const float sigma = fmaxf(rv[c].w, 0.f);
        alpha[c] = 1.f - __expf(-sigma * dist);
        p[c] = 1.f - alpha[c] + 1e-10f;
    }

    // ---- 6 independent inclusive product scans, interleaved for ILP ----
#pragma unroll
    for (int off = 1; off < 32; off <<= 1) {
#pragma unroll
        for (int c = 0; c < NCHUNK; ++c) {
            const float u = __shfl_up_sync(FULL, p[c], off);
            if (lane >= off) p[c] *= u;
        }
    }

    // exclusive prefix within chunk + chunk totals
    float exc[NCHUNK], tot[NCHUNK];
#pragma unroll
    for (int c = 0; c < NCHUNK; ++c) {
        exc[c] = __shfl_up_sync(FULL, p[c], 1);
        if (lane == 0) exc[c] = 1.f;
        tot[c] = __shfl_sync(FULL, p[c], 31);
    }

    // cross-chunk carry prefix
    float carry[NCHUNK];
    carry[0] = 1.f;
#pragma unroll
    for (int c = 1; c < NCHUNK; ++c)
        carry[c] = carry[c - 1] * tot[c - 1];

    // ---- weights, color/depth accumulation, streaming stores ----
    float* __restrict__ wout = out + (long)5 * N;
    float r_sum = 0.f, g_sum = 0.f, b_sum = 0.f, d_sum = 0.f, a_sum = 0.f;

#pragma unroll
    for (int c = 0; c < NCHUNK; ++c) {
        const float w = alpha[c] * carry[c] * exc[c];

        const float sr = fast_sigmoid(rv[c].x);
        const float sg = fast_sigmoid(rv[c].y);
        const float sb = fast_sigmoid(rv[c].z);

        r_sum += w * sr;
        g_sum += w * sg;
        b_sum += w * sb;
        d_sum += w * zv[c];
        a_sum += w;

        __stcs(&wout[base + c * 32 + lane], w);
    }

    // ---- warp reductions ----
#pragma unroll
    for (int off = 16; off; off >>= 1) {
        r_sum += __shfl_down_sync(FULL, r_sum, off);
        g_sum += __shfl_down_sync(FULL, g_sum, off);
        b_sum += __shfl_down_sync(FULL, b_sum, off);
        d_sum += __shfl_down_sync(FULL, d_sum, off);
        a_sum += __shfl_down_sync(FULL, a_sum, off);
    }

    if (lane == 0) {
        out[3 * ray + 0] = r_sum;
        out[3 * ray + 1] = g_sum;
        out[3 * ray + 2] = b_sum;

        const float acc = a_sum;
        float depth = d_sum;
        if (acc <= 1e-10f) depth = INF_DIST;
        const float ratio = __fdividef(depth, acc);
        const float disp  = __fdividef(1.f, fmaxf(1e-10f, ratio));

        out[(long)3 * N + ray]   = disp;
        out[(long)4 * N + ray]   = acc;
        out[(long)197 * N + ray] = depth;
    }
}

extern "C" void kernel_launch(void* const* d_in, const int* in_sizes, int n_in,
                              void* d_out, int out_size)
{
    const float4* raw4   = (const float4*)d_in[0];
    const float*  z_vals = (const float*)d_in[1];
    const float*  rays_d = (const float*)d_in[2];
    float* out = (float*)d_out;

    const int N = in_sizes[2] / 3;          // num rays from rays_d
    const int warps_per_blk = 8;            // 256 threads
    const int blocks = (N + warps_per_blk - 1) / warps_per_blk;
    nerf_render_kernel<<<blocks, warps_per_blk * 32>>>(raw4, z_vals, rays_d, out, N);
}

// round 11
// speedup vs baseline: 1.8532x; 1.0499x over previous
#include <cuda_runtime.h>
#include <cuda_bf16.h>

// NeRF raw2outputs — R11: converged R7 structure + __stwt (write-through)
// on the 52MB write-once weights stream, testing whether removing L2 dirty
// residency smooths HBM read/write turnaround. Everything else identical to
// the 47.6us converged kernel.
//
// One warp per ray, 6 chunks of 32 samples; all 12 global loads front-batched
// (per-warp MLP is the binding resource: regs 48 / occ 52% / DRAM ~80%).
// Single-MUFU tanh.approx sigmoid; 6 interleaved warp product-scans with a
// cross-chunk carry prefix.
//
// Output layout (tuple flattened in order), N = num rays:
//   [0 , 3N)     rgb_map   [N,3]
//   [3N, 4N)     disp_map  [N,1]
//   [4N, 5N)     acc_map   [N,1]
//   [5N, 197N)   weights   [N,192]
//   [197N, 198N) depth_map [N,1]

#define FULL 0xffffffffu
#define NSAMP 192
#define NCHUNK 6
#define INF_DIST 1e10f

__device__ __forceinline__ float fast_sigmoid(float x) {
    float t;
    asm("tanh.approx.f32 %0, %1;" : "=f"(t) : "f"(0.5f * x));
    return fmaf(0.5f, t, 0.5f);
}

__global__ __launch_bounds__(256)
void nerf_render_kernel(const float4* __restrict__ raw4,
                        const float*  __restrict__ z_vals,
                        const float*  __restrict__ rays_d,
                        float* __restrict__ out,
                        int N)
{
    const int warp_in_blk = threadIdx.x >> 5;
    const int lane        = threadIdx.x & 31;
    const int ray = blockIdx.x * (blockDim.x >> 5) + warp_in_blk;
    if (ray >= N) return;

    const long base = (long)ray * NSAMP;

    // ---- front-batch ALL global loads (12 independent LDGs in flight) ----
    float4 rv[NCHUNK];
    float  zv[NCHUNK];
#pragma unroll
    for (int c = 0; c < NCHUNK; ++c)
        rv[c] = __ldcs(&raw4[base + c * 32 + lane]);     // read-once stream
#pragma unroll
    for (int c = 0; c < NCHUNK; ++c)
        zv[c] = __ldcs(&z_vals[base + c * 32 + lane]);   // read-once stream

    const float dx = rays_d[3 * ray + 0];
    const float dy = rays_d[3 * ray + 1];
    const float dz = rays_d[3 * ray + 2];
    const float nrm = sqrtf(dx * dx + dy * dy + dz * dz);

    // ---- per-sample alpha and t = 1-alpha+eps (independent across chunks) ----
    float alpha[NCHUNK], p[NCHUNK];
#pragma unroll
    for (int c = 0; c < NCHUNK; ++c) {
        const float z  = zv[c];
        const float zn = __shfl_down_sync(FULL, z, 1);
        float dist;
        if (c < NCHUNK - 1) {
            const float zfn = __shfl_sync(FULL, zv[c + 1], 0);
            dist = (lane == 31) ? (zfn - z) : (zn - z);
        } else {
            dist = (lane == 31) ? INF_DIST : (zn - z);
        }
        dist *= nrm;
        const float sigma = fmaxf(rv[c].w, 0.f);
        alpha[c] = 1.f - __expf(-sigma * dist);
        p[c] = 1.f - alpha[c] + 1e-10f;
    }

    // ---- 6 independent inclusive product scans, interleaved for ILP ----
#pragma unroll
    for (int off = 1; off < 32; off <<= 1) {
#pragma unroll
        for (int c = 0; c < NCHUNK; ++c) {
            const float u = __shfl_up_sync(FULL, p[c], off);
            if (lane >= off) p[c] *= u;
        }
    }

    // exclusive prefix within chunk + chunk totals
    float exc[NCHUNK], tot[NCHUNK];
#pragma unroll
    for (int c = 0; c < NCHUNK; ++c) {
        exc[c] = __shfl_up_sync(FULL, p[c], 1);
        if (lane == 0) exc[c] = 1.f;
        tot[c] = __shfl_sync(FULL, p[c], 31);
    }

    // cross-chunk carry prefix
    float carry[NCHUNK];
    carry[0] = 1.f;
#pragma unroll
    for (int c = 1; c < NCHUNK; ++c)
        carry[c] = carry[c - 1] * tot[c - 1];

    // ---- weights, color/depth accumulation, write-through stores ----
    float* __restrict__ wout = out + (long)5 * N;
    float r_sum = 0.f, g_sum = 0.f, b_sum = 0.f, d_sum = 0.f, a_sum = 0.f;

#pragma unroll
    for (int c = 0; c < NCHUNK; ++c) {
        const float w = alpha[c] * carry[c] * exc[c];

        const float sr = fast_sigmoid(rv[c].x);
        const float sg = fast_sigmoid(rv[c].y);
        const float sb = fast_sigmoid(rv[c].z);

        r_sum += w * sr;
        g_sum += w * sg;
        b_sum += w * sb;
        d_sum += w * zv[c];
        a_sum += w;

        __stwt(&wout[base + c * 32 + lane], w);   // write-through: no L2 dirty residency
    }

    // ---- warp reductions ----
#pragma unroll
    for (int off = 16; off; off >>= 1) {
        r_sum += __shfl_down_sync(FULL, r_sum, off);
        g_sum += __shfl_down_sync(FULL, g_sum, off);
        b_sum += __shfl_down_sync(FULL, b_sum, off);
        d_sum += __shfl_down_sync(FULL, d_sum, off);
        a_sum += __shfl_down_sync(FULL, a_sum, off);
    }

    if (lane == 0) {
        out[3 * ray + 0] = r_sum;
        out[3 * ray + 1] = g_sum;
        out[3 * ray + 2] = b_sum;

        const float acc = a_sum;
        float depth = d_sum;
        if (acc <= 1e-10f) depth = INF_DIST;
        const float ratio = __fdividef(depth, acc);
        const float disp  = __fdividef(1.f, fmaxf(1e-10f, ratio));

        out[(long)3 * N + ray]   = disp;
        out[(long)4 * N + ray]   = acc;
        out[(long)197 * N + ray] = depth;
    }
}

extern "C" void kernel_launch(void* const* d_in, const int* in_sizes, int n_in,
                              void* d_out, int out_size)
{
    const float4* raw4   = (const float4*)d_in[0];
    const float*  z_vals = (const float*)d_in[1];
    const float*  rays_d = (const float*)d_in[2];
    float* out = (float*)d_out;

    const int N = in_sizes[2] / 3;          // num rays from rays_d
    const int warps_per_blk = 8;            // 256 threads
    const int blocks = (N + warps_per_blk - 1) / warps_per_blk;
    nerf_render_kernel<<<blocks, warps_per_blk * 32>>>(raw4, z_vals, rays_d, out, N);
}